// round 1
// baseline (speedup 1.0000x reference)
#include <cuda_runtime.h>
#include <math.h>

#define SPLINE_ORDER 3
#define GRID_N   16          // GRID_SIZE
#define IN_DIM   64
#define OUT_DIM  64
#define BATCH    1024
#define NCOEF    (GRID_N + SPLINE_ORDER)   // 19

#define BT 32                // batch tile = warp lanes
#define OB 4                 // o-columns per block
#define THREADS 256

// Scratch: packed[o][i][m] = float4(coef[o,i,m], coef[o,i,m+1], coef[o,i,m+2], coef[o,i,m+3])
// 64*64*16 float4 = 1 MB. __device__ global (no allocation in kernel_launch).
__device__ float4 g_packed[OUT_DIM * IN_DIM * GRID_N];

__global__ void pack_coef_kernel(const float* __restrict__ coef) {
    int p = blockIdx.x * blockDim.x + threadIdx.x;
    if (p >= OUT_DIM * IN_DIM * GRID_N) return;
    int m  = p & (GRID_N - 1);
    int oi = p >> 4;
    const float* c = coef + oi * NCOEF + m;
    g_packed[p] = make_float4(c[0], c[1], c[2], c[3]);
}

__global__ __launch_bounds__(THREADS)
void kan_kernel(const float* __restrict__ x,
                const float* __restrict__ grid,
                float* __restrict__ out) {
    // Padded stride 65: lanes-over-b (stride 65) and lanes-over-i (stride 1)
    // are both bank-conflict-free.
    __shared__ float xs[BT * 65];
    __shared__ float S[OB * BT * 65];

    const int b0 = (blockIdx.x & 31) * BT;       // 32 batch tiles
    const int o0 = (blockIdx.x >> 5) * OB;       // 16 o-chunks

    // Stage x[b0..b0+31, :] coalesced into SMEM.
    for (int t = threadIdx.x; t < BT * IN_DIM; t += THREADS) {
        int bb = t >> 6, i = t & 63;
        xs[bb * 65 + i] = x[(b0 + bb) * IN_DIM + i];
    }
    __syncthreads();

    // Uniform grid parameters from input data (exact powers of two here).
    const float g3    = grid[SPLINE_ORDER];          // left edge of live range
    const float h     = grid[SPLINE_ORDER + 1] - g3; // spacing
    const float inv_h = 1.0f / h;
    const float k6    = 1.0f / 6.0f;

    const int lane = threadIdx.x & 31;   // -> batch within tile
    const int warp = threadIdx.x >> 5;   // -> i-group (8 i's per warp)

    #pragma unroll
    for (int ii = 0; ii < IN_DIM / 8; ii++) {
        const int i = warp * 8 + ii;
        const float xv = xs[lane * 65 + i];

        // Knot interval + fractional position (closed-form uniform cubic B-spline).
        float t = (xv - g3) * inv_h;
        int i0 = (int)floorf(t);
        i0 = min(GRID_N - 1, max(0, i0));
        const float u  = t - (float)i0;
        const float om = 1.0f - u;
        const float u2 = u * u, u3 = u2 * u;
        const float w0 = om * om * om * k6;
        const float w1 = (3.0f * u3 - 6.0f * u2 + 4.0f) * k6;
        const float w2 = (-3.0f * u3 + 3.0f * u2 + 3.0f * u + 1.0f) * k6;
        const float w3 = u3 * k6;

        // Lanes (=b) gather within one 256B row of packed -> ~2 wavefronts/LDG.128.
        const float4* p = g_packed + (o0 * IN_DIM + i) * GRID_N + i0;
        #pragma unroll
        for (int oo = 0; oo < OB; oo++) {
            float4 c = p[oo * IN_DIM * GRID_N];
            float r = w0 * c.x;
            r = fmaf(w1, c.y, r);
            r = fmaf(w2, c.z, r);
            r = fmaf(w3, c.w, r);
            S[oo * (BT * 65) + lane * 65 + i] = r;   // conflict-free (stride 65)
        }
    }
    __syncthreads();

    // De-scattered store phase: contiguous 256B rows over i.
    for (int t = threadIdx.x; t < OB * BT * IN_DIM; t += THREADS) {
        int i  = t & 63;
        int r  = t >> 6;        // 0..127
        int bb = r >> 2;
        int oo = r & 3;
        out[((b0 + bb) * OUT_DIM + (o0 + oo)) * IN_DIM + i] =
            S[oo * (BT * 65) + bb * 65 + i];
    }
}

extern "C" void kernel_launch(void* const* d_in, const int* in_sizes, int n_in,
                              void* d_out, int out_size) {
    const float* x    = (const float*)d_in[0];
    const float* coef = (const float*)d_in[1];
    const float* grid = (const float*)d_in[2];
    float* out        = (float*)d_out;

    pack_coef_kernel<<<(OUT_DIM * IN_DIM * GRID_N + 255) / 256, 256>>>(coef);
    kan_kernel<<<(BATCH / BT) * (OUT_DIM / OB), THREADS>>>(x, grid, out);
}